// round 7
// baseline (speedup 1.0000x reference)
#include <cuda_runtime.h>
#include <cuda_bf16.h>
#include <cstdint>

// ---------------------------------------------------------------------------
// CapsuleNetwork forward:
//  conv 9x9 valid + relu -> xf[64][12800]
//  wsum[k][jm] = sum_c W1[j,k,m,c]                (pure 105MB stream)
//  s1[b,jm] = (1/8) * sum_k wsum[k][jm] * xf[b,k] (routing(1) collapses)
//  v1 = squash(s1); u2 = W2 v1; v2 = routing(u2,3) -> out [64,10,16]
// ---------------------------------------------------------------------------

#define B_SZ 64
#define IN_UNITS 12800      // 32*20*20
#define KT2 32              // k per gemm tile
#define NKT2 400            // 12800 / 32

__device__ float g_xf[B_SZ * IN_UNITS];      // 3.28 MB [b][k]
__device__ float g_wsum[IN_UNITS * 64];      // 3.28 MB [k][j*8+m]
__device__ float g_part[NKT2 * B_SZ * 64];   // 6.55 MB [kt][b][jm]

// ---------------------------------------------------------------------------
// Kernel 1: conv 9x9 valid + bias + relu -> xf[b][c*400 + y*20 + x]
// 640 blocks x 256 threads; thread = (c, y, x-quarter), 5 outputs each.
// ---------------------------------------------------------------------------
__global__ __launch_bounds__(256) void conv_kernel(
    const float* __restrict__ x, const float* __restrict__ w,
    const float* __restrict__ bias)
{
    __shared__ float xs[784];
    __shared__ float wsm[2592];

    int b = blockIdx.x / 10, q = blockIdx.x % 10;
    int t = threadIdx.x;

    for (int i = t; i < 784; i += 256) xs[i] = x[b * 784 + i];
    for (int i = t; i < 2592; i += 256) wsm[i] = w[i];
    __syncthreads();

    int idx = q * 256 + t;          // 0..2559
    int c = idx / 80, r = idx % 80;
    int y = r >> 2, x0 = (r & 3) * 5;

    float acc0 = 0.f, acc1 = 0.f, acc2 = 0.f, acc3 = 0.f, acc4 = 0.f;

    for (int i = 0; i < 9; i++) {
        float wr[9];
        #pragma unroll
        for (int jj = 0; jj < 9; jj++) wr[jj] = wsm[c * 81 + i * 9 + jj];
        float xr[13];
        #pragma unroll
        for (int u = 0; u < 13; u++) xr[u] = xs[(y + i) * 28 + x0 + u];
        #pragma unroll
        for (int jj = 0; jj < 9; jj++) {
            acc0 = fmaf(xr[0 + jj], wr[jj], acc0);
            acc1 = fmaf(xr[1 + jj], wr[jj], acc1);
            acc2 = fmaf(xr[2 + jj], wr[jj], acc2);
            acc3 = fmaf(xr[3 + jj], wr[jj], acc3);
            acc4 = fmaf(xr[4 + jj], wr[jj], acc4);
        }
    }

    float bv = bias[c];
    float* dst = &g_xf[(size_t)b * IN_UNITS + c * 400 + y * 20 + x0];
    dst[0] = fmaxf(acc0 + bv, 0.f);
    dst[1] = fmaxf(acc1 + bv, 0.f);
    dst[2] = fmaxf(acc2 + bv, 0.f);
    dst[3] = fmaxf(acc3 + bv, 0.f);
    dst[4] = fmaxf(acc4 + bv, 0.f);
}

// ---------------------------------------------------------------------------
// Kernel 2: PURE W1 stream -> wsum (c-reduction). 800 blocks x 128 threads,
// 16 k per block. Software-pipelined 8-deep float4 batches across the j loop.
// No smem, no __syncthreads.
// ---------------------------------------------------------------------------
__global__ __launch_bounds__(128) void wsum_kernel(const float* __restrict__ W1)
{
    int ht = blockIdx.x;       // 0..799 : k = ht*16 .. +16
    int t  = threadIdx.x;      // 0..127

    const float4* __restrict__ Wv = (const float4*)W1;
    size_t base = (size_t)ht * 1024;      // f4 offset of this k-range (j=0)

    float4 cur[8], nxt[8];
    #pragma unroll
    for (int q = 0; q < 8; q++) cur[q] = Wv[base + q * 128 + t];

    #pragma unroll
    for (int j = 0; j < 8; j++) {
        if (j < 7) {
            size_t nb = base + (size_t)(j + 1) * 819200;
            #pragma unroll
            for (int q = 0; q < 8; q++) nxt[q] = Wv[nb + q * 128 + t];
        }
        #pragma unroll
        for (int q = 0; q < 8; q++) {
            float p = (cur[q].x + cur[q].y) + (cur[q].z + cur[q].w);
            p += __shfl_xor_sync(0xffffffffu, p, 1);
            p += __shfl_xor_sync(0xffffffffu, p, 2);
            p += __shfl_xor_sync(0xffffffffu, p, 4);
            if ((t & 7) == 0) {
                int r = q * 128 + t;              // element/8 within 1024-f4 tile
                int k_l = r >> 6, m = (r >> 3) & 7;
                g_wsum[(size_t)(ht * 16 + k_l) * 64 + j * 8 + m] = p;
            }
        }
        if (j < 7) {
            #pragma unroll
            for (int q = 0; q < 8; q++) cur[q] = nxt[q];
        }
    }
}

// ---------------------------------------------------------------------------
// Kernel 3: s1 partial GEMM per 32-k tile (L2-resident operands).
// 256 threads: thread = (bq in 16) x (jq in 16), 4b x 4jm outputs.
// ---------------------------------------------------------------------------
__global__ __launch_bounds__(256) void gemm_kernel()
{
    int kt = blockIdx.x;       // 0..399
    int t  = threadIdx.x;

    __shared__ float xsT[KT2 * 68];   // [kk][b]
    __shared__ float ws[KT2 * 68];    // [kk][jm]

    {
        const float4* src = (const float4*)&g_wsum[(size_t)kt * KT2 * 64];
        #pragma unroll
        for (int q = 0; q < 2; q++) {
            int f4 = q * 256 + t;
            int kk = f4 >> 4, col = (f4 & 15) * 4;
            *(float4*)&ws[kk * 68 + col] = src[f4];
        }
    }
    {
        int bb = t >> 2, kq = t & 3;
        const float* src = &g_xf[(size_t)bb * IN_UNITS + kt * KT2 + kq * 8];
        float4 a = *(const float4*)&src[0];
        float4 c = *(const float4*)&src[4];
        int k0 = kq * 8;
        xsT[(k0 + 0) * 68 + bb] = a.x;
        xsT[(k0 + 1) * 68 + bb] = a.y;
        xsT[(k0 + 2) * 68 + bb] = a.z;
        xsT[(k0 + 3) * 68 + bb] = a.w;
        xsT[(k0 + 4) * 68 + bb] = c.x;
        xsT[(k0 + 5) * 68 + bb] = c.y;
        xsT[(k0 + 6) * 68 + bb] = c.z;
        xsT[(k0 + 7) * 68 + bb] = c.w;
    }
    __syncthreads();

    int bq = t >> 4;      // b = 4*bq..
    int jq = t & 15;      // jm = 4*jq..

    float a00=0.f,a01=0.f,a02=0.f,a03=0.f, a10=0.f,a11=0.f,a12=0.f,a13=0.f;
    float a20=0.f,a21=0.f,a22=0.f,a23=0.f, a30=0.f,a31=0.f,a32=0.f,a33=0.f;

    #pragma unroll
    for (int kk = 0; kk < KT2; kk++) {
        float4 xv = *(const float4*)&xsT[kk * 68 + bq * 4];
        float4 wv = *(const float4*)&ws[kk * 68 + jq * 4];
        a00 = fmaf(xv.x, wv.x, a00); a01 = fmaf(xv.x, wv.y, a01);
        a02 = fmaf(xv.x, wv.z, a02); a03 = fmaf(xv.x, wv.w, a03);
        a10 = fmaf(xv.y, wv.x, a10); a11 = fmaf(xv.y, wv.y, a11);
        a12 = fmaf(xv.y, wv.z, a12); a13 = fmaf(xv.y, wv.w, a13);
        a20 = fmaf(xv.z, wv.x, a20); a21 = fmaf(xv.z, wv.y, a21);
        a22 = fmaf(xv.z, wv.z, a22); a23 = fmaf(xv.z, wv.w, a23);
        a30 = fmaf(xv.w, wv.x, a30); a31 = fmaf(xv.w, wv.y, a31);
        a32 = fmaf(xv.w, wv.z, a32); a33 = fmaf(xv.w, wv.w, a33);
    }

    float* dst = &g_part[(size_t)kt * 4096 + (bq * 4) * 64 + jq * 4];
    *(float4*)&dst[0]   = make_float4(a00, a01, a02, a03);
    *(float4*)&dst[64]  = make_float4(a10, a11, a12, a13);
    *(float4*)&dst[128] = make_float4(a20, a21, a22, a23);
    *(float4*)&dst[192] = make_float4(a30, a31, a32, a33);
}

// ---------------------------------------------------------------------------
// Kernel 4: reduce 400 partials (fixed order), squash -> v1, digit caps,
// routing(3), output. One block per batch, 512 threads.
// ---------------------------------------------------------------------------
__global__ __launch_bounds__(512) void caps2_kernel(
    const float* __restrict__ W2, float* __restrict__ out)
{
    int b = blockIdx.x;
    int t = threadIdx.x;

    __shared__ float ps[8 * 64];
    __shared__ float ss[64];
    __shared__ float v1s[64];
    __shared__ float es[80];
    __shared__ float bs[80];
    __shared__ float ds[8];

    {
        int jm = t & 63, s = t >> 6;
        const float* src = &g_part[(size_t)(s * 50) * 4096 + b * 64 + jm];
        float acc = 0.f;
        #pragma unroll
        for (int q = 0; q < 50; q++) acc += src[(size_t)q * 4096];
        ps[s * 64 + jm] = acc;
    }
    __syncthreads();
    if (t < 64) {
        float s = 0.f;
        #pragma unroll
        for (int i = 0; i < 8; i++) s += ps[i * 64 + t];
        ss[t] = s * 0.125f;
    }
    __syncthreads();
    if (t < 64) {
        int jj = t >> 3;
        float nsq = 0.f;
        #pragma unroll
        for (int mm = 0; mm < 8; mm++) { float v = ss[jj * 8 + mm]; nsq = fmaf(v, v, nsq); }
        float n = sqrtf(nsq);
        v1s[t] = ss[t] * (n / (1.f + nsq));
    }
    if (t < 80) bs[t] = 0.f;
    __syncthreads();

    bool act = (t < 160);
    int jraw = t >> 4;
    int j = (jraw < 10) ? jraw : 0;
    int m = t & 15;

    float u2r[8];
    const float4* W2v = (const float4*)W2;
    const float4* v1v = (const float4*)v1s;
    #pragma unroll
    for (int k = 0; k < 8; k++) {
        int base = ((j * 8 + k) * 16 + m) * 2;
        float4 wa = W2v[base], wb = W2v[base + 1];
        float4 va = v1v[k * 2], vb = v1v[k * 2 + 1];
        u2r[k] = wa.x * va.x + wa.y * va.y + wa.z * va.z + wa.w * va.w
               + wb.x * vb.x + wb.y * vb.y + wb.z * vb.z + wb.w * vb.w;
    }

    float v = 0.f;
    for (int it = 0; it < 3; it++) {
        if (t < 80) es[t] = expf(bs[t]);
        __syncthreads();
        if (t < 8) {
            float d = 0.f;
            #pragma unroll
            for (int jj = 0; jj < 10; jj++) d += es[jj * 8 + t];
            ds[t] = d;
        }
        __syncthreads();
        float s = 0.f;
        #pragma unroll
        for (int k = 0; k < 8; k++)
            s = fmaf(es[j * 8 + k] / ds[k], u2r[k], s);
        float p = s * s;
        p += __shfl_xor_sync(0xffffffffu, p, 1);
        p += __shfl_xor_sync(0xffffffffu, p, 2);
        p += __shfl_xor_sync(0xffffffffu, p, 4);
        p += __shfl_xor_sync(0xffffffffu, p, 8);
        float n = sqrtf(p);
        v = s * (n / (1.f + p));
        __syncthreads();
        if (it < 2) {
            #pragma unroll
            for (int k = 0; k < 8; k++) {
                float q = u2r[k] * v;
                q += __shfl_xor_sync(0xffffffffu, q, 1);
                q += __shfl_xor_sync(0xffffffffu, q, 2);
                q += __shfl_xor_sync(0xffffffffu, q, 4);
                q += __shfl_xor_sync(0xffffffffu, q, 8);
                if (act && m == 0) bs[j * 8 + k] += q;
            }
        }
        __syncthreads();
    }

    if (act) out[b * 160 + t] = v;
}

// ---------------------------------------------------------------------------
extern "C" void kernel_launch(void* const* d_in, const int* in_sizes, int n_in,
                              void* d_out, int out_size)
{
    const float* x      = (const float*)d_in[0];  // [64,1,28,28]
    const float* conv_w = (const float*)d_in[1];  // [32,1,9,9]
    const float* conv_b = (const float*)d_in[2];  // [32]
    const float* W1     = (const float*)d_in[3];  // [8,12800,8,32]
    const float* W2     = (const float*)d_in[4];  // [10,8,16,8]
    float* out = (float*)d_out;                   // [64,10,16]

    wsum_kernel<<<800, 128>>>(W1);
    conv_kernel<<<640, 256>>>(x, conv_w, conv_b);
    gemm_kernel<<<400, 256>>>();
    caps2_kernel<<<B_SZ, 512>>>(W2, out);
}

// round 8
// speedup vs baseline: 1.0993x; 1.0993x over previous
#include <cuda_runtime.h>
#include <cuda_bf16.h>
#include <cstdint>

// ---------------------------------------------------------------------------
// CapsuleNetwork forward:
//  conv 9x9 valid + relu -> xf[64][12800]
//  s1[b,jm] = (1/8) * sum_k (sum_c W1[j,k,m,c]) * xf[b,k]   (routing(1) collapses)
//  v1 = squash(s1); u2 = W2 v1; v2 = routing(u2,3) -> out [64,10,16]
//
//  conv   : high-occupancy direct conv                         (~5us)
//  caps1  : fused W1 stream + c-reduce + GEMM vs xf -> g_part  (~16us, HBM roofline)
//  reduce : parallel 400->8 partial reduction (float4, hi MLP) (~2us)
//  routing: 8->1 reduce, squash, digit caps, routing(3)        (~1.5us)
// ---------------------------------------------------------------------------

#define B_SZ 64
#define IN_UNITS 12800      // 32*20*20
#define KT2 32              // k per caps1 tile
#define NKT2 400            // 12800 / 32

__device__ float g_xf[B_SZ * IN_UNITS];      // 3.28 MB [b][k]
__device__ float g_part[NKT2 * B_SZ * 64];   // 6.55 MB [kt][b][jm]
__device__ float g_s1p[8 * B_SZ * 64];       // 128 KB  [s][b][jm]

// ---------------------------------------------------------------------------
// Kernel 1: conv 9x9 valid + bias + relu -> xf[b][c*400 + y*20 + x]
// 640 blocks x 256 threads; thread = (c, y, x-quarter), 5 outputs each.
// ---------------------------------------------------------------------------
__global__ __launch_bounds__(256) void conv_kernel(
    const float* __restrict__ x, const float* __restrict__ w,
    const float* __restrict__ bias)
{
    __shared__ float xs[784];
    __shared__ float wsm[2592];

    int b = blockIdx.x / 10, q = blockIdx.x % 10;
    int t = threadIdx.x;

    for (int i = t; i < 784; i += 256) xs[i] = x[b * 784 + i];
    for (int i = t; i < 2592; i += 256) wsm[i] = w[i];
    __syncthreads();

    int idx = q * 256 + t;          // 0..2559
    int c = idx / 80, r = idx % 80;
    int y = r >> 2, x0 = (r & 3) * 5;

    float acc0 = 0.f, acc1 = 0.f, acc2 = 0.f, acc3 = 0.f, acc4 = 0.f;

    for (int i = 0; i < 9; i++) {
        float wr[9];
        #pragma unroll
        for (int jj = 0; jj < 9; jj++) wr[jj] = wsm[c * 81 + i * 9 + jj];
        float xr[13];
        #pragma unroll
        for (int u = 0; u < 13; u++) xr[u] = xs[(y + i) * 28 + x0 + u];
        #pragma unroll
        for (int jj = 0; jj < 9; jj++) {
            acc0 = fmaf(xr[0 + jj], wr[jj], acc0);
            acc1 = fmaf(xr[1 + jj], wr[jj], acc1);
            acc2 = fmaf(xr[2 + jj], wr[jj], acc2);
            acc3 = fmaf(xr[3 + jj], wr[jj], acc3);
            acc4 = fmaf(xr[4 + jj], wr[jj], acc4);
        }
    }

    float bv = bias[c];
    float* dst = &g_xf[(size_t)b * IN_UNITS + c * 400 + y * 20 + x0];
    dst[0] = fmaxf(acc0 + bv, 0.f);
    dst[1] = fmaxf(acc1 + bv, 0.f);
    dst[2] = fmaxf(acc2 + bv, 0.f);
    dst[3] = fmaxf(acc3 + bv, 0.f);
    dst[4] = fmaxf(acc4 + bv, 0.f);
}

// ---------------------------------------------------------------------------
// Kernel 2 (R3-proven, ~7TB/s effective): W1 stream + c-reduce + GEMM vs xf.
// grid NKT2=400 (kt), 512 threads. Writes deterministic partials g_part.
// ---------------------------------------------------------------------------
__global__ __launch_bounds__(512) void caps1_kernel(const float* __restrict__ W1)
{
    int kt = blockIdx.x;       // 0..399
    int t  = threadIdx.x;      // 0..511

    __shared__ float xsT[KT2 * 68];   // [kk][b], row stride 68
    __shared__ float ws[KT2 * 68];    // [kk][jm], row stride 68

    // load xf tile transposed: thread (b = t>>3, k4 = t&7) loads float4
    {
        int bb = t >> 3, k4 = t & 7;
        float4 xv = *(const float4*)&g_xf[(size_t)bb * IN_UNITS + kt * KT2 + k4 * 4];
        xsT[(k4 * 4 + 0) * 68 + bb] = xv.x;
        xsT[(k4 * 4 + 1) * 68 + bb] = xv.y;
        xsT[(k4 * 4 + 2) * 68 + bb] = xv.z;
        xsT[(k4 * 4 + 3) * 68 + bb] = xv.w;
    }

    // phase 1: W1 stream + c-reduction
    const float4* __restrict__ Wv = (const float4*)W1;
    int lanec = t & 7;
    #pragma unroll
    for (int j = 0; j < 8; j++) {
        size_t base = (size_t)j * 819200 + (size_t)kt * 2048;   // float4 units
        #pragma unroll
        for (int i = 0; i < 4; i++) {
            int idx = i * 512 + t;
            float4 v = Wv[base + idx];
            float p = (v.x + v.y) + (v.z + v.w);
            p += __shfl_xor_sync(0xffffffffu, p, 1);
            p += __shfl_xor_sync(0xffffffffu, p, 2);
            p += __shfl_xor_sync(0xffffffffu, p, 4);
            if (lanec == 0) {
                int r = idx >> 3;               // kk*8 + m
                ws[(r >> 3) * 68 + j * 8 + (r & 7)] = p;
            }
        }
    }
    __syncthreads();

    // phase 2: s1 partial GEMM [64b x 64jm] over this 32-k tile
    int bq  = t >> 5;     // 0..15 -> b = 4*bq..
    int jm2 = t & 31;     // 0..31 -> jm = 2*jm2..

    float a0 = 0.f, a1 = 0.f, a2 = 0.f, a3 = 0.f;
    float a4 = 0.f, a5 = 0.f, a6 = 0.f, a7 = 0.f;

    #pragma unroll
    for (int kk = 0; kk < KT2; kk++) {
        float4 xv = *(const float4*)&xsT[kk * 68 + bq * 4];
        float2 wv = *(const float2*)&ws[kk * 68 + jm2 * 2];
        a0 = fmaf(xv.x, wv.x, a0);
        a1 = fmaf(xv.y, wv.x, a1);
        a2 = fmaf(xv.z, wv.x, a2);
        a3 = fmaf(xv.w, wv.x, a3);
        a4 = fmaf(xv.x, wv.y, a4);
        a5 = fmaf(xv.y, wv.y, a5);
        a6 = fmaf(xv.z, wv.y, a6);
        a7 = fmaf(xv.w, wv.y, a7);
    }

    float* dst = &g_part[(size_t)kt * 4096];
    int col = jm2 * 2;
    dst[(bq * 4 + 0) * 64 + col]     = a0;
    dst[(bq * 4 + 1) * 64 + col]     = a1;
    dst[(bq * 4 + 2) * 64 + col]     = a2;
    dst[(bq * 4 + 3) * 64 + col]     = a3;
    dst[(bq * 4 + 0) * 64 + col + 1] = a4;
    dst[(bq * 4 + 1) * 64 + col + 1] = a5;
    dst[(bq * 4 + 2) * 64 + col + 1] = a6;
    dst[(bq * 4 + 3) * 64 + col + 1] = a7;
}

// ---------------------------------------------------------------------------
// Kernel 3: parallel partial reduction 400 -> 8.
// grid 512 = (b, s in 8); 128 threads = (g in 8) x (c4 in 16 float4 cols).
// Each thread sums ~6 float4 (contiguous 128B per warp-load), smem tree 8->1.
// ---------------------------------------------------------------------------
__global__ __launch_bounds__(128) void reduce_kernel()
{
    int bx = blockIdx.x;
    int s = bx & 7, b = bx >> 3;
    int t = threadIdx.x;
    int c4 = t & 15, g = t >> 4;

    __shared__ float4 red[8][16];

    float4 acc = make_float4(0.f, 0.f, 0.f, 0.f);
    for (int q = g; q < 50; q += 8) {
        int kt = s * 50 + q;
        float4 v = *(const float4*)&g_part[(size_t)kt * 4096 + b * 64 + c4 * 4];
        acc.x += v.x; acc.y += v.y; acc.z += v.z; acc.w += v.w;
    }
    red[g][c4] = acc;
    __syncthreads();

    if (t < 16) {
        float4 a = red[0][t];
        #pragma unroll
        for (int i = 1; i < 8; i++) {
            float4 v = red[i][t];
            a.x += v.x; a.y += v.y; a.z += v.z; a.w += v.w;
        }
        *(float4*)&g_s1p[(size_t)s * 4096 + b * 64 + t * 4] = a;
    }
}

// ---------------------------------------------------------------------------
// Kernel 4: final 8->1 reduce, squash -> v1, digit caps, routing(3), output.
// One block per batch, 192 threads.
// ---------------------------------------------------------------------------
__global__ __launch_bounds__(192) void routing_kernel(
    const float* __restrict__ W2, float* __restrict__ out)
{
    int b = blockIdx.x;
    int t = threadIdx.x;

    __shared__ float ss[64];
    __shared__ float v1s[64];
    __shared__ float es[80];
    __shared__ float bs[80];
    __shared__ float ds[8];

    if (t < 64) {
        float s = 0.f;
        #pragma unroll
        for (int i = 0; i < 8; i++) s += g_s1p[(size_t)i * 4096 + b * 64 + t];
        ss[t] = s * 0.125f;
    }
    __syncthreads();
    if (t < 64) {
        int jj = t >> 3;
        float nsq = 0.f;
        #pragma unroll
        for (int mm = 0; mm < 8; mm++) { float v = ss[jj * 8 + mm]; nsq = fmaf(v, v, nsq); }
        float n = sqrtf(nsq);
        v1s[t] = ss[t] * (n / (1.f + nsq));
    }
    if (t < 80) bs[t] = 0.f;
    __syncthreads();

    bool act = (t < 160);
    int jraw = t >> 4;
    int j = (jraw < 10) ? jraw : 0;
    int m = t & 15;

    float u2r[8];
    const float4* W2v = (const float4*)W2;
    const float4* v1v = (const float4*)v1s;
    #pragma unroll
    for (int k = 0; k < 8; k++) {
        int base = ((j * 8 + k) * 16 + m) * 2;
        float4 wa = W2v[base], wb = W2v[base + 1];
        float4 va = v1v[k * 2], vb = v1v[k * 2 + 1];
        u2r[k] = wa.x * va.x + wa.y * va.y + wa.z * va.z + wa.w * va.w
               + wb.x * vb.x + wb.y * vb.y + wb.z * vb.z + wb.w * vb.w;
    }

    float v = 0.f;
    for (int it = 0; it < 3; it++) {
        if (t < 80) es[t] = expf(bs[t]);
        __syncthreads();
        if (t < 8) {
            float d = 0.f;
            #pragma unroll
            for (int jj = 0; jj < 10; jj++) d += es[jj * 8 + t];
            ds[t] = d;
        }
        __syncthreads();
        float s = 0.f;
        #pragma unroll
        for (int k = 0; k < 8; k++)
            s = fmaf(es[j * 8 + k] / ds[k], u2r[k], s);
        float p = s * s;
        p += __shfl_xor_sync(0xffffffffu, p, 1);
        p += __shfl_xor_sync(0xffffffffu, p, 2);
        p += __shfl_xor_sync(0xffffffffu, p, 4);
        p += __shfl_xor_sync(0xffffffffu, p, 8);
        float n = sqrtf(p);
        v = s * (n / (1.f + p));
        __syncthreads();
        if (it < 2) {
            #pragma unroll
            for (int k = 0; k < 8; k++) {
                float q = u2r[k] * v;
                q += __shfl_xor_sync(0xffffffffu, q, 1);
                q += __shfl_xor_sync(0xffffffffu, q, 2);
                q += __shfl_xor_sync(0xffffffffu, q, 4);
                q += __shfl_xor_sync(0xffffffffu, q, 8);
                if (act && m == 0) bs[j * 8 + k] += q;
            }
        }
        __syncthreads();
    }

    if (act) out[b * 160 + t] = v;
}

// ---------------------------------------------------------------------------
extern "C" void kernel_launch(void* const* d_in, const int* in_sizes, int n_in,
                              void* d_out, int out_size)
{
    const float* x      = (const float*)d_in[0];  // [64,1,28,28]
    const float* conv_w = (const float*)d_in[1];  // [32,1,9,9]
    const float* conv_b = (const float*)d_in[2];  // [32]
    const float* W1     = (const float*)d_in[3];  // [8,12800,8,32]
    const float* W2     = (const float*)d_in[4];  // [10,8,16,8]
    float* out = (float*)d_out;                   // [64,10,16]

    conv_kernel<<<640, 256>>>(x, conv_w, conv_b);
    caps1_kernel<<<NKT2, 512>>>(W1);
    reduce_kernel<<<512, 128>>>();
    routing_kernel<<<B_SZ, 192>>>(W2, out);
}

// round 9
// speedup vs baseline: 1.1811x; 1.0744x over previous
#include <cuda_runtime.h>
#include <cuda_bf16.h>
#include <cstdint>

// ---------------------------------------------------------------------------
// CapsuleNetwork forward:
//  conv 9x9 valid + relu -> xf[64][12800]
//  s1[b,jm] = (1/8) * sum_k (sum_c W1[j,k,m,c]) * xf[b,k]   (routing(1) collapses)
//  v1 = squash(s1); u2 = W2 v1; v2 = routing(u2,3) -> out [64,10,16]
//
//  conv  : high-occupancy direct conv
//  caps1 : fused W1 stream + c-reduce + GEMM vs xf -> g_part (HBM roofline)
//  final : parallel 400-slice reduce + squash + digit caps + routing(3)
// ---------------------------------------------------------------------------

#define B_SZ 64
#define IN_UNITS 12800      // 32*20*20
#define KT2 32              // k per caps1 tile
#define NKT2 400            // 12800 / 32

__device__ float g_xf[B_SZ * IN_UNITS];      // 3.28 MB [b][k]
__device__ float g_part[NKT2 * B_SZ * 64];   // 6.55 MB [kt][b][jm]

// ---------------------------------------------------------------------------
// Kernel 1: conv 9x9 valid + bias + relu -> xf[b][c*400 + y*20 + x]
// 640 blocks x 256 threads; thread = (c, y, x-quarter), 5 outputs each.
// ---------------------------------------------------------------------------
__global__ __launch_bounds__(256) void conv_kernel(
    const float* __restrict__ x, const float* __restrict__ w,
    const float* __restrict__ bias)
{
    __shared__ float xs[784];
    __shared__ float wsm[2592];

    int b = blockIdx.x / 10, q = blockIdx.x % 10;
    int t = threadIdx.x;

    for (int i = t; i < 784; i += 256) xs[i] = x[b * 784 + i];
    for (int i = t; i < 2592; i += 256) wsm[i] = w[i];
    __syncthreads();

    int idx = q * 256 + t;          // 0..2559
    int c = idx / 80, r = idx % 80;
    int y = r >> 2, x0 = (r & 3) * 5;

    float acc0 = 0.f, acc1 = 0.f, acc2 = 0.f, acc3 = 0.f, acc4 = 0.f;

    for (int i = 0; i < 9; i++) {
        float wr[9];
        #pragma unroll
        for (int jj = 0; jj < 9; jj++) wr[jj] = wsm[c * 81 + i * 9 + jj];
        float xr[13];
        #pragma unroll
        for (int u = 0; u < 13; u++) xr[u] = xs[(y + i) * 28 + x0 + u];
        #pragma unroll
        for (int jj = 0; jj < 9; jj++) {
            acc0 = fmaf(xr[0 + jj], wr[jj], acc0);
            acc1 = fmaf(xr[1 + jj], wr[jj], acc1);
            acc2 = fmaf(xr[2 + jj], wr[jj], acc2);
            acc3 = fmaf(xr[3 + jj], wr[jj], acc3);
            acc4 = fmaf(xr[4 + jj], wr[jj], acc4);
        }
    }

    float bv = bias[c];
    float* dst = &g_xf[(size_t)b * IN_UNITS + c * 400 + y * 20 + x0];
    dst[0] = fmaxf(acc0 + bv, 0.f);
    dst[1] = fmaxf(acc1 + bv, 0.f);
    dst[2] = fmaxf(acc2 + bv, 0.f);
    dst[3] = fmaxf(acc3 + bv, 0.f);
    dst[4] = fmaxf(acc4 + bv, 0.f);
}

// ---------------------------------------------------------------------------
// Kernel 2 (R3-proven): W1 stream + c-reduce + GEMM vs xf -> g_part.
// grid NKT2=400 (kt), 512 threads. Deterministic partials, no atomics.
// ---------------------------------------------------------------------------
__global__ __launch_bounds__(512) void caps1_kernel(const float* __restrict__ W1)
{
    int kt = blockIdx.x;       // 0..399
    int t  = threadIdx.x;      // 0..511

    __shared__ float xsT[KT2 * 68];   // [kk][b], row stride 68
    __shared__ float ws[KT2 * 68];    // [kk][jm], row stride 68

    // load xf tile transposed: thread (b = t>>3, k4 = t&7) loads float4
    {
        int bb = t >> 3, k4 = t & 7;
        float4 xv = *(const float4*)&g_xf[(size_t)bb * IN_UNITS + kt * KT2 + k4 * 4];
        xsT[(k4 * 4 + 0) * 68 + bb] = xv.x;
        xsT[(k4 * 4 + 1) * 68 + bb] = xv.y;
        xsT[(k4 * 4 + 2) * 68 + bb] = xv.z;
        xsT[(k4 * 4 + 3) * 68 + bb] = xv.w;
    }

    // phase 1: W1 stream + c-reduction
    const float4* __restrict__ Wv = (const float4*)W1;
    int lanec = t & 7;
    #pragma unroll
    for (int j = 0; j < 8; j++) {
        size_t base = (size_t)j * 819200 + (size_t)kt * 2048;   // float4 units
        #pragma unroll
        for (int i = 0; i < 4; i++) {
            int idx = i * 512 + t;
            float4 v = Wv[base + idx];
            float p = (v.x + v.y) + (v.z + v.w);
            p += __shfl_xor_sync(0xffffffffu, p, 1);
            p += __shfl_xor_sync(0xffffffffu, p, 2);
            p += __shfl_xor_sync(0xffffffffu, p, 4);
            if (lanec == 0) {
                int r = idx >> 3;               // kk*8 + m
                ws[(r >> 3) * 68 + j * 8 + (r & 7)] = p;
            }
        }
    }
    __syncthreads();

    // phase 2: s1 partial GEMM [64b x 64jm] over this 32-k tile
    int bq  = t >> 5;     // 0..15 -> b = 4*bq..
    int jm2 = t & 31;     // 0..31 -> jm = 2*jm2..

    float a0 = 0.f, a1 = 0.f, a2 = 0.f, a3 = 0.f;
    float a4 = 0.f, a5 = 0.f, a6 = 0.f, a7 = 0.f;

    #pragma unroll
    for (int kk = 0; kk < KT2; kk++) {
        float4 xv = *(const float4*)&xsT[kk * 68 + bq * 4];
        float2 wv = *(const float2*)&ws[kk * 68 + jm2 * 2];
        a0 = fmaf(xv.x, wv.x, a0);
        a1 = fmaf(xv.y, wv.x, a1);
        a2 = fmaf(xv.z, wv.x, a2);
        a3 = fmaf(xv.w, wv.x, a3);
        a4 = fmaf(xv.x, wv.y, a4);
        a5 = fmaf(xv.y, wv.y, a5);
        a6 = fmaf(xv.z, wv.y, a6);
        a7 = fmaf(xv.w, wv.y, a7);
    }

    float* dst = &g_part[(size_t)kt * 4096];
    int col = jm2 * 2;
    dst[(bq * 4 + 0) * 64 + col]     = a0;
    dst[(bq * 4 + 1) * 64 + col]     = a1;
    dst[(bq * 4 + 2) * 64 + col]     = a2;
    dst[(bq * 4 + 3) * 64 + col]     = a3;
    dst[(bq * 4 + 0) * 64 + col + 1] = a4;
    dst[(bq * 4 + 1) * 64 + col + 1] = a5;
    dst[(bq * 4 + 2) * 64 + col + 1] = a6;
    dst[(bq * 4 + 3) * 64 + col + 1] = a7;
}

// ---------------------------------------------------------------------------
// Kernel 3: final. One block per batch b, 256 threads.
//  - reduce 400 partial slices: thread=(s in 16, c4 in 16), 25 float4 each
//  - squash -> v1; u2 = W2 v1; routing(3) with smem-dot b-updates (no long
//    shfl chains), __expf + reciprocal softmax.
// ---------------------------------------------------------------------------
__global__ __launch_bounds__(256) void final_kernel(
    const float* __restrict__ W2, float* __restrict__ out)
{
    int b = blockIdx.x;
    int t = threadIdx.x;

    __shared__ float red[16][68];     // [slice][jm]
    __shared__ float ss[64];          // s1
    __shared__ float v1s[64];         // v1
    __shared__ float u2s[80][17];     // u2[j*8+k][m]
    __shared__ float vs[160];         // current v[j][m]
    __shared__ float es[80];          // exp(logits)
    __shared__ float bs_s[80];        // routing logits
    __shared__ float inv_ds[8];       // 1/softmax-denominator per k

    // ---- parallel partial reduction: 400 slices -> 16 -> 1 ----
    {
        int c4 = t & 15, s = t >> 4;
        const float* src = &g_part[(size_t)(s * 25) * 4096 + b * 64 + c4 * 4];
        float4 acc = make_float4(0.f, 0.f, 0.f, 0.f);
        #pragma unroll
        for (int q = 0; q < 25; q++) {
            float4 v = *(const float4*)&src[(size_t)q * 4096];
            acc.x += v.x; acc.y += v.y; acc.z += v.z; acc.w += v.w;
        }
        red[s][c4 * 4 + 0] = acc.x;
        red[s][c4 * 4 + 1] = acc.y;
        red[s][c4 * 4 + 2] = acc.z;
        red[s][c4 * 4 + 3] = acc.w;
    }
    __syncthreads();
    if (t < 64) {
        float s = 0.f;
        #pragma unroll
        for (int i = 0; i < 16; i++) s += red[i][t];
        ss[t] = s * 0.125f;
    }
    __syncthreads();
    if (t < 64) {
        int jj = t >> 3;
        float nsq = 0.f;
        #pragma unroll
        for (int mm = 0; mm < 8; mm++) { float v = ss[jj * 8 + mm]; nsq = fmaf(v, v, nsq); }
        float n = sqrtf(nsq);
        v1s[t] = ss[t] * (n / (1.f + nsq));
    }
    if (t < 80) bs_s[t] = 0.f;
    __syncthreads();

    bool act = (t < 160);
    int jraw = t >> 4;
    int j = (jraw < 10) ? jraw : 0;
    int m = t & 15;

    // u2[j][k][m] in registers + smem copy for the b-update dots
    float u2r[8];
    const float4* W2v = (const float4*)W2;
    const float4* v1v = (const float4*)v1s;
    #pragma unroll
    for (int k = 0; k < 8; k++) {
        int base = ((j * 8 + k) * 16 + m) * 2;
        float4 wa = W2v[base], wb = W2v[base + 1];
        float4 va = v1v[k * 2], vb = v1v[k * 2 + 1];
        u2r[k] = wa.x * va.x + wa.y * va.y + wa.z * va.z + wa.w * va.w
               + wb.x * vb.x + wb.y * vb.y + wb.z * vb.z + wb.w * vb.w;
        if (act) u2s[j * 8 + k][m] = u2r[k];
    }
    __syncthreads();

    float v = 0.f;
    for (int it = 0; it < 3; it++) {
        if (t < 80) es[t] = __expf(bs_s[t]);
        __syncthreads();
        if (t < 8) {
            float d = 0.f;
            #pragma unroll
            for (int jj = 0; jj < 10; jj++) d += es[jj * 8 + t];
            inv_ds[t] = 1.f / d;
        }
        __syncthreads();
        float s = 0.f;
        #pragma unroll
        for (int k = 0; k < 8; k++)
            s = fmaf(es[j * 8 + k] * inv_ds[k], u2r[k], s);
        float p = s * s;
        p += __shfl_xor_sync(0xffffffffu, p, 1);
        p += __shfl_xor_sync(0xffffffffu, p, 2);
        p += __shfl_xor_sync(0xffffffffu, p, 4);
        p += __shfl_xor_sync(0xffffffffu, p, 8);
        float n = sqrtf(p);
        v = s * (n / (1.f + p));
        if (act) vs[t] = v;
        __syncthreads();
        if (it < 2) {
            if (t < 80) {
                const float* uv = u2s[t];
                const float* vv = &vs[(t >> 3) * 16];
                float q = 0.f;
                #pragma unroll
                for (int mm = 0; mm < 16; mm++) q = fmaf(uv[mm], vv[mm], q);
                bs_s[t] += q;
            }
            __syncthreads();
        }
    }

    if (act) out[b * 160 + t] = v;
}

// ---------------------------------------------------------------------------
extern "C" void kernel_launch(void* const* d_in, const int* in_sizes, int n_in,
                              void* d_out, int out_size)
{
    const float* x      = (const float*)d_in[0];  // [64,1,28,28]
    const float* conv_w = (const float*)d_in[1];  // [32,1,9,9]
    const float* conv_b = (const float*)d_in[2];  // [32]
    const float* W1     = (const float*)d_in[3];  // [8,12800,8,32]
    const float* W2     = (const float*)d_in[4];  // [10,8,16,8]
    float* out = (float*)d_out;                   // [64,10,16]

    conv_kernel<<<640, 256>>>(x, conv_w, conv_b);
    caps1_kernel<<<NKT2, 512>>>(W1);
    final_kernel<<<B_SZ, 256>>>(W2, out);
}

// round 11
// speedup vs baseline: 1.2482x; 1.0568x over previous
#include <cuda_runtime.h>
#include <cuda_bf16.h>
#include <cstdint>

// ---------------------------------------------------------------------------
// CapsuleNetwork forward, 2 kernels:
//  mega : per block (c, 2 conv rows = 40 k):
//          - in-smem conv for its own xf tile (no g_xf round trip)
//          - stream W1[j, 40k, 8m, 32c] (327KB/block), c-reduce -> ws smem
//          - GEMM [64b x 64jm] over 40 k -> deterministic g_part slice
//  final: 320-slice reduce + squash + digit caps + routing(3)
// ---------------------------------------------------------------------------

#define B_SZ 64
#define IN_UNITS 12800      // 32*20*20
#define KT 40               // k per tile = 2 rows x 20
#define NKT 320             // 12800 / 40

__device__ float g_part[NKT * B_SZ * 64];    // 5.24 MB [kt][b][jm]

// dynamic smem layout (floats)
#define SM_IMG   0                    // [64][284]  10 rows x 28 + pad
#define SM_XST   18176                // [40][68]   xf tile transposed [kk][b]
#define SM_WS    20896                // [40][68]   wsum tile [kk][jm]
#define SM_WSM   23616                // [82]       conv weights + bias
#define SM_TOTAL 23698                // floats -> 94792 bytes

__global__ __launch_bounds__(512) void mega_kernel(
    const float* __restrict__ x, const float* __restrict__ w,
    const float* __restrict__ bias, const float* __restrict__ W1)
{
    extern __shared__ float sm[];
    float* img = sm + SM_IMG;
    float* xsT = sm + SM_XST;
    float* ws  = sm + SM_WS;
    float* wsm = sm + SM_WSM;

    int bid = blockIdx.x;        // 0..319 ; k0 = bid*40
    int t = threadIdx.x;         // 0..511
    int c = bid / 10;            // conv channel
    int y0 = (bid % 10) * 2;     // first of 2 output rows

    const float4* __restrict__ Wv = (const float4*)W1;
    size_t base0 = (size_t)bid * 2560;          // f4 offset, j=0

    // ---- issue first stream batch early (DRAM busy during conv) ----
    float4 cur[5], nxt[5];
    #pragma unroll
    for (int q = 0; q < 5; q++) cur[q] = Wv[base0 + q * 512 + t];

    // ---- cooperative image rows load: rows y0..y0+9, all 64 b ----
    {
        const float* xb = x + y0 * 28;
        for (int i = t; i < 4480; i += 512) {
            int bb = i / 70, off = (i % 70) * 4;
            *(float4*)&img[bb * 284 + off] = *(const float4*)&xb[bb * 784 + off];
        }
    }
    if (t < 81) wsm[t] = w[c * 81 + t];
    if (t == 81) wsm[81] = bias[c];
    __syncthreads();

    // ---- conv: thread = (b = t>>3, yl = (t>>2)&1, xq = t&3), 5 outputs ----
    {
        int b = t >> 3, yl = (t >> 2) & 1, x0 = (t & 3) * 5;
        float bv = wsm[81];
        float a0 = 0.f, a1 = 0.f, a2 = 0.f, a3 = 0.f, a4 = 0.f;
        const float* ib = &img[b * 284 + yl * 28 + x0];
        #pragma unroll
        for (int i = 0; i < 9; i++) {
            float wr[9];
            #pragma unroll
            for (int jj = 0; jj < 9; jj++) wr[jj] = wsm[i * 9 + jj];
            float xr[13];
            #pragma unroll
            for (int u = 0; u < 13; u++) xr[u] = ib[i * 28 + u];
            #pragma unroll
            for (int jj = 0; jj < 9; jj++) {
                a0 = fmaf(xr[0 + jj], wr[jj], a0);
                a1 = fmaf(xr[1 + jj], wr[jj], a1);
                a2 = fmaf(xr[2 + jj], wr[jj], a2);
                a3 = fmaf(xr[3 + jj], wr[jj], a3);
                a4 = fmaf(xr[4 + jj], wr[jj], a4);
            }
        }
        int kk0 = yl * 20 + x0;
        xsT[(kk0 + 0) * 68 + b] = fmaxf(a0 + bv, 0.f);
        xsT[(kk0 + 1) * 68 + b] = fmaxf(a1 + bv, 0.f);
        xsT[(kk0 + 2) * 68 + b] = fmaxf(a2 + bv, 0.f);
        xsT[(kk0 + 3) * 68 + b] = fmaxf(a3 + bv, 0.f);
        xsT[(kk0 + 4) * 68 + b] = fmaxf(a4 + bv, 0.f);
    }

    // ---- W1 stream, 8 j batches, prefetch-pipelined; c-reduce -> ws ----
    int lanec = t & 7;
    #pragma unroll
    for (int j = 0; j < 8; j++) {
        if (j < 7) {
            size_t nb = base0 + (size_t)(j + 1) * 819200;
            #pragma unroll
            for (int q = 0; q < 5; q++) nxt[q] = Wv[nb + q * 512 + t];
        }
        #pragma unroll
        for (int q = 0; q < 5; q++) {
            float p = (cur[q].x + cur[q].y) + (cur[q].z + cur[q].w);
            p += __shfl_xor_sync(0xffffffffu, p, 1);
            p += __shfl_xor_sync(0xffffffffu, p, 2);
            p += __shfl_xor_sync(0xffffffffu, p, 4);
            if (lanec == 0) {
                int r = (q * 512 + t) >> 3;        // kk*8 + m
                ws[(r >> 3) * 68 + j * 8 + (r & 7)] = p;
            }
        }
        if (j < 7) {
            #pragma unroll
            for (int q = 0; q < 5; q++) cur[q] = nxt[q];
        }
    }
    __syncthreads();

    // ---- GEMM [64b x 64jm] over 40 k ----
    int bq  = t >> 5;     // 0..15 -> b = 4*bq..
    int jm2 = t & 31;     // 0..31 -> jm = 2*jm2..

    float a0 = 0.f, a1 = 0.f, a2 = 0.f, a3 = 0.f;
    float a4 = 0.f, a5 = 0.f, a6 = 0.f, a7 = 0.f;

    #pragma unroll
    for (int kk = 0; kk < KT; kk++) {
        float4 xv = *(const float4*)&xsT[kk * 68 + bq * 4];
        float2 wv = *(const float2*)&ws[kk * 68 + jm2 * 2];
        a0 = fmaf(xv.x, wv.x, a0);
        a1 = fmaf(xv.y, wv.x, a1);
        a2 = fmaf(xv.z, wv.x, a2);
        a3 = fmaf(xv.w, wv.x, a3);
        a4 = fmaf(xv.x, wv.y, a4);
        a5 = fmaf(xv.y, wv.y, a5);
        a6 = fmaf(xv.z, wv.y, a6);
        a7 = fmaf(xv.w, wv.y, a7);
    }

    float* dst = &g_part[(size_t)bid * 4096];
    int col = jm2 * 2;
    dst[(bq * 4 + 0) * 64 + col]     = a0;
    dst[(bq * 4 + 1) * 64 + col]     = a1;
    dst[(bq * 4 + 2) * 64 + col]     = a2;
    dst[(bq * 4 + 3) * 64 + col]     = a3;
    dst[(bq * 4 + 0) * 64 + col + 1] = a4;
    dst[(bq * 4 + 1) * 64 + col + 1] = a5;
    dst[(bq * 4 + 2) * 64 + col + 1] = a6;
    dst[(bq * 4 + 3) * 64 + col + 1] = a7;
}

// ---------------------------------------------------------------------------
// Kernel 2: final. One block per batch b, 256 threads.
//  - reduce 320 partial slices: thread=(s in 16, c4 in 16), 20 float4 each
//  - squash -> v1; u2 = W2 v1; routing(3) with smem-dot b-updates.
// ---------------------------------------------------------------------------
__global__ __launch_bounds__(256) void final_kernel(
    const float* __restrict__ W2, float* __restrict__ out)
{
    int b = blockIdx.x;
    int t = threadIdx.x;

    __shared__ float red[16][68];     // [slice][jm]
    __shared__ float ss[64];          // s1
    __shared__ float v1s[64];         // v1
    __shared__ float u2s[80][17];     // u2[j*8+k][m]
    __shared__ float vs[160];         // current v[j][m]
    __shared__ float es[80];          // exp(logits)
    __shared__ float bs_s[80];        // routing logits
    __shared__ float inv_ds[8];       // 1/softmax-denominator per k

    // ---- parallel partial reduction: 320 slices -> 16 -> 1 ----
    {
        int c4 = t & 15, s = t >> 4;
        const float* src = &g_part[(size_t)(s * 20) * 4096 + b * 64 + c4 * 4];
        float4 acc = make_float4(0.f, 0.f, 0.f, 0.f);
        #pragma unroll
        for (int q = 0; q < 20; q++) {
            float4 v = *(const float4*)&src[(size_t)q * 4096];
            acc.x += v.x; acc.y += v.y; acc.z += v.z; acc.w += v.w;
        }
        red[s][c4 * 4 + 0] = acc.x;
        red[s][c4 * 4 + 1] = acc.y;
        red[s][c4 * 4 + 2] = acc.z;
        red[s][c4 * 4 + 3] = acc.w;
    }
    __syncthreads();
    if (t < 64) {
        float s = 0.f;
        #pragma unroll
        for (int i = 0; i < 16; i++) s += red[i][t];
        ss[t] = s * 0.125f;
    }
    __syncthreads();
    if (t < 64) {
        int jj = t >> 3;
        float nsq = 0.f;
        #pragma unroll
        for (int mm = 0; mm < 8; mm++) { float v = ss[jj * 8 + mm]; nsq = fmaf(v, v, nsq); }
        float n = sqrtf(nsq);
        v1s[t] = ss[t] * (n / (1.f + nsq));
    }
    if (t < 80) bs_s[t] = 0.f;
    __syncthreads();

    bool act = (t < 160);
    int jraw = t >> 4;
    int j = (jraw < 10) ? jraw : 0;
    int m = t & 15;

    float u2r[8];
    const float4* W2v = (const float4*)W2;
    const float4* v1v = (const float4*)v1s;
    #pragma unroll
    for (int k = 0; k < 8; k++) {
        int base = ((j * 8 + k) * 16 + m) * 2;
        float4 wa = W2v[base], wb = W2v[base + 1];
        float4 va = v1v[k * 2], vb = v1v[k * 2 + 1];
        u2r[k] = wa.x * va.x + wa.y * va.y + wa.z * va.z + wa.w * va.w
               + wb.x * vb.x + wb.y * vb.y + wb.z * vb.z + wb.w * vb.w;
        if (act) u2s[j * 8 + k][m] = u2r[k];
    }
    __syncthreads();

    float v = 0.f;
    for (int it = 0; it < 3; it++) {
        if (t < 80) es[t] = __expf(bs_s[t]);
        __syncthreads();
        if (t < 8) {
            float d = 0.f;
            #pragma unroll
            for (int jj = 0; jj < 10; jj++) d += es[jj * 8 + t];
            inv_ds[t] = 1.f / d;
        }
        __syncthreads();
        float s = 0.f;
        #pragma unroll
        for (int k = 0; k < 8; k++)
            s = fmaf(es[j * 8 + k] * inv_ds[k], u2r[k], s);
        float p = s * s;
        p += __shfl_xor_sync(0xffffffffu, p, 1);
        p += __shfl_xor_sync(0xffffffffu, p, 2);
        p += __shfl_xor_sync(0xffffffffu, p, 4);
        p += __shfl_xor_sync(0xffffffffu, p, 8);
        float n = sqrtf(p);
        v = s * (n / (1.f + p));
        if (act) vs[t] = v;
        __syncthreads();
        if (it < 2) {
            if (t < 80) {
                const float* uv = u2s[t];
                const float* vv = &vs[(t >> 3) * 16];
                float q = 0.f;
                #pragma unroll
                for (int mm = 0; mm < 16; mm++) q = fmaf(uv[mm], vv[mm], q);
                bs_s[t] += q;
            }
            __syncthreads();
        }
    }

    if (act) out[b * 160 + t] = v;
}

// ---------------------------------------------------------------------------
extern "C" void kernel_launch(void* const* d_in, const int* in_sizes, int n_in,
                              void* d_out, int out_size)
{
    const float* x      = (const float*)d_in[0];  // [64,1,28,28]
    const float* conv_w = (const float*)d_in[1];  // [32,1,9,9]
    const float* conv_b = (const float*)d_in[2];  // [32]
    const float* W1     = (const float*)d_in[3];  // [8,12800,8,32]
    const float* W2     = (const float*)d_in[4];  // [10,8,16,8]
    float* out = (float*)d_out;                   // [64,10,16]

    cudaFuncSetAttribute(mega_kernel,
                         cudaFuncAttributeMaxDynamicSharedMemorySize,
                         SM_TOTAL * 4);

    mega_kernel<<<NKT, 512, SM_TOTAL * 4>>>(x, conv_w, conv_b, W1);
    final_kernel<<<B_SZ, 256>>>(W2, out);
}